// round 13
// baseline (speedup 1.0000x reference)
#include <cuda_runtime.h>
#include <cuda_fp16.h>
#include <cstdint>

#define TOKS 14
#define MTILES 15         // ceil(238/16) m-tiles
#define THREADS 256
#define HSTR 72           // half stride for T0 rows (144B, conflict-free)
#define YSTR 68           // float stride for Yf

// smem byte offsets
#define T0_OFF   0                  // 240 x HSTR half  (A1 tile)   34560
#define YF_OFF   34560              // 240 x YSTR float (Y tile)    65280
#define B2F_OFF  99840              // 4ks x 8nt x 32 x uint2 = 8192
#define B3F_OFF  108032             // 4ks x 4nt x 32 x uint2 = 4096
#define XS_OFF   112128             // 14 tokens x 17 float2 = 1904
#define SMEM_BYTES 114032           // x2 = 228064 <= 228KB/SM -> 2 CTAs

__device__ __forceinline__ void mma16(float c[4], const uint32_t a[4], uint32_t b0, uint32_t b1) {
    asm volatile(
        "mma.sync.aligned.m16n8k16.row.col.f32.f16.f16.f32 "
        "{%0,%1,%2,%3}, {%4,%5,%6,%7}, {%8,%9}, {%0,%1,%2,%3};"
        : "+f"(c[0]), "+f"(c[1]), "+f"(c[2]), "+f"(c[3])
        : "r"(a[0]), "r"(a[1]), "r"(a[2]), "r"(a[3]), "r"(b0), "r"(b1));
}

__device__ __forceinline__ uint32_t h2pack(float a, float b) {
    __half2 h = __floats2half2_rn(a, b);
    return *(uint32_t*)&h;
}

// unrolled skeleton aggregation (adj + I, all-ones)
__device__ __forceinline__ void aggF(const float* s, float* g) {
    g[0]  = s[0] + s[1] + s[2] + s[5] + s[6];
    g[1]  = s[1] + s[0] + s[3];
    g[2]  = s[2] + s[0] + s[4];
    g[3]  = s[3] + s[1];
    g[4]  = s[4] + s[2];
    g[5]  = s[5] + s[0] + s[7] + s[11];
    g[6]  = s[6] + s[0] + s[8] + s[12];
    g[7]  = s[7] + s[5] + s[9];
    g[8]  = s[8] + s[6] + s[10];
    g[9]  = s[9] + s[7];
    g[10] = s[10] + s[8];
    g[11] = s[11] + s[5] + s[13];
    g[12] = s[12] + s[6] + s[14];
    g[13] = s[13] + s[11] + s[15];
    g[14] = s[14] + s[12] + s[16];
    g[15] = s[15] + s[13];
    g[16] = s[16] + s[14];
}

extern __shared__ char smem[];

__global__ void __launch_bounds__(THREADS, 2)
sge_h(const float* __restrict__ x,
      const float* __restrict__ W1, const float* __restrict__ b1,
      const float* __restrict__ W2, const float* __restrict__ b2,
      const float* __restrict__ W3, const float* __restrict__ b3,
      float* __restrict__ out, int NT, int nstages)
{
    const int tid = threadIdx.x;
    const int warp = tid >> 5, lane = tid & 31;
    const int g = lane >> 2, q = lane & 3;

    __half* T0 = (__half*)(smem + T0_OFF);
    float*  Yf = (float*)(smem + YF_OFF);
    uint2*  B2f = (uint2*)(smem + B2F_OFF);
    uint2*  B3f = (uint2*)(smem + B3F_OFF);
    float2* xs = (float2*)(smem + XS_OFF);

    // ---- init: pack W2/W3 into per-lane m16n8k16 fp16 B fragments ----
    for (int idx = tid; idx < 4 * 8 * 32; idx += THREADS) {
        int l = idx & 31, nt = (idx >> 5) & 7, ks = idx >> 8;
        int gg = l >> 2, qq = l & 3, n = nt * 8 + gg, k0 = ks * 16 + 2 * qq;
        uint2 v;
        v.x = h2pack(W2[k0 * 64 + n],       W2[(k0 + 1) * 64 + n]);
        v.y = h2pack(W2[(k0 + 8) * 64 + n], W2[(k0 + 9) * 64 + n]);
        B2f[idx] = v;
    }
    for (int idx = tid; idx < 4 * 4 * 32; idx += THREADS) {
        int l = idx & 31, nt = (idx >> 5) & 3, ks = idx >> 7;
        int gg = l >> 2, qq = l & 3, n = nt * 8 + gg, k0 = ks * 16 + 2 * qq;
        uint2 v;
        v.x = h2pack(W3[k0 * 32 + n],       W3[(k0 + 1) * 32 + n]);
        v.y = h2pack(W3[(k0 + 8) * 32 + n], W3[(k0 + 9) * 32 + n]);
        B3f[idx] = v;
    }
    for (int i = tid; i < (240 * HSTR) / 2; i += THREADS)
        ((uint32_t*)T0)[i] = 0u;   // zero T0, pad rows 238..239 stay 0

    // per-lane layer-1 weights/biases for features {2*lane, 2*lane+1}
    const float wA0 = __ldg(W1 + 2 * lane),     wA1 = __ldg(W1 + 64 + 2 * lane);
    const float wB0 = __ldg(W1 + 2 * lane + 1), wB1 = __ldg(W1 + 64 + 2 * lane + 1);
    const float bA  = __ldg(b1 + 2 * lane),     bB  = __ldg(b1 + 2 * lane + 1);
    const float b3r = __ldg(b3 + lane);

    // b2 fragments: warp covers all 64 N cols
    float2 b2p[8];
    #pragma unroll
    for (int nt = 0; nt < 8; nt++) {
        int cb = nt * 8 + 2 * q;
        b2p[nt] = make_float2(b2[cb], b2[cb + 1]);
    }

    // ---- initial x prefetch: warp handles tokens {warp, warp+8} ----
    float2 xc[2];
    #pragma unroll
    for (int ti = 0; ti < 2; ti++) {
        int tt = warp + ti * 8;
        int tg = blockIdx.x * TOKS + tt;
        xc[ti] = make_float2(0.f, 0.f);
        if (tt < TOKS && lane < 17 && tg < NT)
            xc[ti] = __ldg((const float2*)x + (size_t)tg * 17 + lane);
    }
    __syncthreads();

    int ptok0 = 0, pvtok = 0;   // previous stage pending Y

    for (int s = blockIdx.x; s < nstages; s += gridDim.x) {
        const int tok0 = s * TOKS;
        const int vtok = min(TOKS, NT - tok0);

        // ---- stage x, prefetch next ----
        #pragma unroll
        for (int ti = 0; ti < 2; ti++) {
            int tt = warp + ti * 8;
            if (tt < TOKS && lane < 17) xs[tt * 17 + lane] = xc[ti];
        }
        {
            int ns = s + gridDim.x;
            #pragma unroll
            for (int ti = 0; ti < 2; ti++) {
                int tt = warp + ti * 8;
                int tg = ns * TOKS + tt;
                xc[ti] = make_float2(0.f, 0.f);
                if (tt < TOKS && lane < 17 && ns < nstages && tg < NT)
                    xc[ti] = __ldg((const float2*)x + (size_t)tg * 17 + lane);
            }
        }
        __syncwarp();

        // ---- phase A1: layer 1 + agg (warp-local, 2 tokens) -> T0 (fp16) ----
        #pragma unroll 1
        for (int ti = 0; ti < 2; ti++) {
            int t = warp + ti * 8;
            if (t < vtok) {
                const float2* xb = xs + t * 17;
                float xax[17], xay[17];
                #pragma unroll
                for (int j = 0; j < 17; j++) { float2 v = xb[j]; xax[j] = v.x; xay[j] = v.y; }
                float gx[17], gy[17];
                aggF(xax, gx); aggF(xay, gy);

                float h[17], ga[17], gb[17];
                #pragma unroll
                for (int j = 0; j < 17; j++)
                    h[j] = fmaxf(fmaf(gx[j], wA0, fmaf(gy[j], wA1, bA)), 0.f);
                aggF(h, ga);
                #pragma unroll
                for (int j = 0; j < 17; j++)
                    h[j] = fmaxf(fmaf(gx[j], wB0, fmaf(gy[j], wB1, bB)), 0.f);
                aggF(h, gb);

                uint32_t* au = (uint32_t*)(T0 + (17 * t) * HSTR + 2 * lane);
                #pragma unroll
                for (int j = 0; j < 17; j++)
                    au[j * (HSTR / 2)] = h2pack(ga[j], gb[j]);
            }
        }

        // ---- phase A2: out = agg(prev Y) + b3 -> gmem (2 tokens) ----
        #pragma unroll 1
        for (int ti = 0; ti < 2; ti++) {
            int t = warp + ti * 8;
            if (t < pvtok) {
                const float* yc = Yf + (t * 17) * YSTR + lane;
                float y[17];
                #pragma unroll
                for (int j = 0; j < 17; j++) y[j] = yc[j * YSTR];
                float o[17];
                aggF(y, o);
                float* ob = out + ((size_t)(ptok0 + t) * 17) * 32 + lane;
                #pragma unroll
                for (int j = 0; j < 17; j++) ob[j * 32] = o[j] + b3r;
            }
        }
        __syncthreads();   // T0 ready, prev Y consumed

        // ---- phase B: per m-tile: GEMM1 (16x64) -> regs -> GEMM2 (16x32) -> Yf ----
        #pragma unroll 1
        for (int mi = 0; mi < 2; mi++) {
            int mt = warp + mi * 8;
            if (mt >= MTILES) break;
            const int r0 = mt * 16 + g;

            float c1[8][4];
            #pragma unroll
            for (int nt = 0; nt < 8; nt++)
                #pragma unroll
                for (int i = 0; i < 4; i++) c1[nt][i] = 0.f;

            const __half* ar = T0 + r0 * HSTR;
            #pragma unroll
            for (int ks = 0; ks < 4; ks++) {
                const int k0 = ks * 16 + 2 * q;
                uint32_t a[4];
                a[0] = *(const uint32_t*)(ar + k0);
                a[1] = *(const uint32_t*)(ar + 8 * HSTR + k0);
                a[2] = *(const uint32_t*)(ar + k0 + 8);
                a[3] = *(const uint32_t*)(ar + 8 * HSTR + k0 + 8);
                const uint2* bf = B2f + ks * 256 + lane;
                #pragma unroll
                for (int nt = 0; nt < 8; nt++) {
                    uint2 b = bf[nt * 32];
                    mma16(c1[nt], a, b.x, b.y);
                }
            }

            // bias + relu + pack: C-frags == A-frags for GEMM2
            uint32_t a2[4][4];
            #pragma unroll
            for (int kt = 0; kt < 4; kt++) {
                const float2 blo = b2p[2 * kt], bhi = b2p[2 * kt + 1];
                a2[kt][0] = h2pack(fmaxf(c1[2 * kt][0] + blo.x, 0.f),
                                   fmaxf(c1[2 * kt][1] + blo.y, 0.f));
                a2[kt][1] = h2pack(fmaxf(c1[2 * kt][2] + blo.x, 0.f),
                                   fmaxf(c1[2 * kt][3] + blo.y, 0.f));
                a2[kt][2] = h2pack(fmaxf(c1[2 * kt + 1][0] + bhi.x, 0.f),
                                   fmaxf(c1[2 * kt + 1][1] + bhi.y, 0.f));
                a2[kt][3] = h2pack(fmaxf(c1[2 * kt + 1][2] + bhi.x, 0.f),
                                   fmaxf(c1[2 * kt + 1][3] + bhi.y, 0.f));
            }

            float c2[4][4];
            #pragma unroll
            for (int nt = 0; nt < 4; nt++)
                #pragma unroll
                for (int i = 0; i < 4; i++) c2[nt][i] = 0.f;

            #pragma unroll
            for (int kt = 0; kt < 4; kt++) {
                const uint2* bf = B3f + kt * 128 + lane;
                #pragma unroll
                for (int nt = 0; nt < 4; nt++) {
                    uint2 b = bf[nt * 32];
                    mma16(c2[nt], a2[kt], b.x, b.y);
                }
            }
            #pragma unroll
            for (int nt = 0; nt < 4; nt++) {
                int cb = nt * 8 + 2 * q;
                *(float2*)(Yf + r0 * YSTR + cb) = make_float2(c2[nt][0], c2[nt][1]);
                *(float2*)(Yf + (r0 + 8) * YSTR + cb) = make_float2(c2[nt][2], c2[nt][3]);
            }
        }
        ptok0 = tok0; pvtok = vtok;
        __syncthreads();   // Y ready; T0 free for next stage
    }

    // ---- tail: flush last stage's Y ----
    #pragma unroll 1
    for (int ti = 0; ti < 2; ti++) {
        int t = warp + ti * 8;
        if (t < pvtok) {
            const float* yc = Yf + (t * 17) * YSTR + lane;
            float y[17];
            #pragma unroll
            for (int j = 0; j < 17; j++) y[j] = yc[j * YSTR];
            float o[17];
            aggF(y, o);
            float* ob = out + ((size_t)(ptok0 + t) * 17) * 32 + lane;
            #pragma unroll
            for (int j = 0; j < 17; j++) ob[j * 32] = o[j] + b3r;
        }
    }
}

extern "C" void kernel_launch(void* const* d_in, const int* in_sizes, int n_in,
                              void* d_out, int out_size) {
    const float* x  = (const float*)d_in[0];
    const float* W1 = (const float*)d_in[1];
    const float* b1 = (const float*)d_in[2];
    const float* W2 = (const float*)d_in[3];
    const float* b2 = (const float*)d_in[4];
    const float* W3 = (const float*)d_in[5];
    const float* b3 = (const float*)d_in[6];
    float* out = (float*)d_out;

    const int NT = in_sizes[0] / (17 * 2);          // 65536 tokens
    const int nstages = (NT + TOKS - 1) / TOKS;     // 4682

    static int attr_done = 0;
    if (!attr_done) {
        cudaFuncSetAttribute(sge_h, cudaFuncAttributeMaxDynamicSharedMemorySize, SMEM_BYTES);
        attr_done = 1;
    }
    int grid = nstages < 296 ? nstages : 296;
    sge_h<<<grid, THREADS, SMEM_BYTES>>>(x, W1, b1, W2, b2, W3, b3, out, NT, nstages);
}